// round 3
// baseline (speedup 1.0000x reference)
#include <cuda_runtime.h>
#include <cuda_bf16.h>
#include <cstdint>
#include <cstddef>

#define BB 256
#define TT 512
#define II 128
#define HH 256
#define SS 4
#define KK 384            /* H + I */
#define NROWS 1024        /* 4H */
#define NBLK 128
#define NGRP 8
#define BLK_PER_GRP 16

#define A_STRIDE 392      /* 384 + 8 pad (bf16 elems) to break LDS bank conflicts */
#define G_STRIDE 65       /* gate smem row stride (floats) */

/* shared memory layout (bytes) */
#define SM_AHI   0
#define SM_ALO   25088                 /* 32*392*2 */
#define SM_GATES 50176                 /* 32*65*4 = 8320 */
#define SM_BIAS  58496                 /* 4*64*4 = 1024 */
#define SM_LEN   59520                 /* 32*4 */
#define SM_BG    59648                 /* 32*4 */
#define SM_SEG   59776                 /* 32*4 */
#define SMEM_BYTES 59904

/* ------------------------------------------------------------------ */
/* device globals (scratch; static __device__ arrays are allowed)      */
/* ------------------------------------------------------------------ */
__device__ int d_len[BB];
__device__ int d_sorted[BB];        /* sorted position -> global batch  */
__device__ int d_len_sorted[BB];
__device__ __nv_bfloat16 d_Whi[SS * NROWS * KK];
__device__ __nv_bfloat16 d_Wlo[SS * NROWS * KK];
__device__ float d_bias[SS * NROWS];
__device__ float d_h[2][BB * HH];   /* h state by sorted position, ping-pong */
__device__ unsigned d_cnt[NGRP];
__device__ unsigned d_phase[NGRP];

/* ------------------------------------------------------------------ */
/* setup: mask dtype sniff, lengths, counting sort by length           */
/* ------------------------------------------------------------------ */
__global__ void setup_kernel(const void* mask)
{
    const int tid = threadIdx.x;
    const unsigned char* mb = (const unsigned char*)mask;

    /* mask[0][0] and [0][1] are guaranteed true (lengths >= 256).
       u8 bool : 01 01 ...      -> mb[0]==1, mb[1]==1
       int32   : 01 00 00 00    -> mb[0]==1, mb[1]==0
       float32 : 00 00 80 3f    -> mb[0]==0, mb[1]==0
       fp16    : 00 3c          -> mb[0]==0, mb[1]!=0
       bf16    : 80 3f          -> mb[0]==0x80                         */
    int mode;
    if (mb[0] == 1 && mb[1] == 1)      mode = 0;   /* u8  */
    else if (mb[0] == 1)               mode = 1;   /* i32 */
    else if (mb[0] == 0 && mb[1] == 0) mode = 2;   /* f32 */
    else                               mode = 3;   /* 16-bit */

    if (tid < BB) {
        int cnt = 0;
        for (int t = 0; t < TT; ++t) {
            long idx = (long)tid * TT + t;
            bool v;
            if (mode == 0)      v = mb[idx] != 0;
            else if (mode == 1) v = ((const int*)mask)[idx] != 0;
            else if (mode == 2) v = ((const float*)mask)[idx] != 0.0f;
            else                v = ((const unsigned short*)mask)[idx] != 0;
            cnt += v ? 1 : 0;
        }
        if (cnt < 1) cnt = 1;
        d_len[tid] = cnt;
    }
    __syncthreads();
    if (tid < BB) {
        int L = d_len[tid];
        int r = 0;
        for (int b = 0; b < BB; ++b) {
            int Lb = d_len[b];
            if (Lb < L || (Lb == L && b < tid)) r++;
        }
        d_sorted[r] = tid;
        d_len_sorted[r] = L;
    }
    if (tid == 0) {
        for (int g = 0; g < NGRP; ++g) { d_cnt[g] = 0u; d_phase[g] = 0u; }
    }
}

/* ------------------------------------------------------------------ */
/* pack: [W_hh | W_ih] -> bf16 hi/lo planes; bias sum; zero h[0]       */
/* ------------------------------------------------------------------ */
__global__ void pack_kernel(const float* __restrict__ Wih,
                            const float* __restrict__ Whh,
                            const float* __restrict__ bih,
                            const float* __restrict__ bhh)
{
    const int totalW = SS * NROWS * KK;            /* 1,572,864 */
    const int totalB = SS * NROWS;                 /* 4096 */
    const int totalH = BB * HH;                    /* 65536 */
    const int total  = totalW + totalB + totalH;
    for (int i = blockIdx.x * blockDim.x + threadIdx.x; i < total;
         i += gridDim.x * blockDim.x) {
        if (i < totalW) {
            int k   = i % KK;
            int rr  = i / KK;
            int row = rr % NROWS;
            int s   = rr / NROWS;
            float w = (k < HH)
                ? Whh[((size_t)s * NROWS + row) * HH + k]
                : Wih[((size_t)s * NROWS + row) * II + (k - HH)];
            __nv_bfloat16 hi = __float2bfloat16(w);
            float rem = w - __bfloat162float(hi);
            d_Whi[i] = hi;
            d_Wlo[i] = __float2bfloat16(rem);
        } else if (i < totalW + totalB) {
            int j = i - totalW;
            d_bias[j] = bih[j] + bhh[j];
        } else {
            int j = i - totalW - totalB;
            d_h[0][j] = 0.0f;
        }
    }
}

/* ------------------------------------------------------------------ */
/* mma helper: m16n8k16 row.col f32.bf16.bf16.f32                      */
/* ------------------------------------------------------------------ */
#define MMA_BF16(acc, a0, a1, a2, a3, b0, b1)                               \
    asm volatile(                                                           \
        "mma.sync.aligned.m16n8k16.row.col.f32.bf16.bf16.f32 "              \
        "{%0,%1,%2,%3}, {%4,%5,%6,%7}, {%8,%9}, {%0,%1,%2,%3};"             \
        : "+f"((acc)[0]), "+f"((acc)[1]), "+f"((acc)[2]), "+f"((acc)[3])    \
        : "r"(a0), "r"(a1), "r"(a2), "r"(a3), "r"(b0), "r"(b1))

/* ------------------------------------------------------------------ */
/* persistent LSTM kernel: 128 CTAs = 8 batch-groups x 16 h-slices     */
/* ------------------------------------------------------------------ */
__global__ void __launch_bounds__(256, 1)
lstm_kernel(const float* __restrict__ x, float* __restrict__ out)
{
    extern __shared__ unsigned char sm[];
    __nv_bfloat16* Ahi = (__nv_bfloat16*)(sm + SM_AHI);
    __nv_bfloat16* Alo = (__nv_bfloat16*)(sm + SM_ALO);
    float* Gm  = (float*)(sm + SM_GATES);
    float* Bs  = (float*)(sm + SM_BIAS);
    int*   Lsm = (int*)(sm + SM_LEN);
    int*   BGs = (int*)(sm + SM_BG);
    int*   SGs = (int*)(sm + SM_SEG);

    const int tid  = threadIdx.x;
    const int bid  = blockIdx.x;
    const int grp  = bid >> 4;      /* batch group 0..7   */
    const int nsl  = bid & 15;      /* h-slice     0..15  */
    const int warp = tid >> 5, lane = tid & 31;
    const int wm = warp >> 2, wn = warp & 3;   /* 2 M-warps x 4 N-warps (N-warp == gate type) */
    const int g  = lane >> 2, tig = lane & 3;
    const int row_base = wm * 16;

    if (tid < 32) {
        int p = grp * 32 + tid;
        BGs[tid] = d_sorted[p];
        Lsm[tid] = d_len_sorted[p];
    }
    {   /* bias cache: [seg][type*16+hl] for this block's 64 gate rows */
        int s = tid >> 6, c = tid & 63;
        int type = c >> 4, hl = c & 15;
        Bs[tid] = d_bias[s * NROWS + type * 256 + nsl * 16 + hl];
    }
    __syncthreads();

    /* each thread statically owns 2 (batch,h) cells: p=tid and p=tid+256 */
    float hreg[2] = {0.0f, 0.0f};
    float creg[2] = {0.0f, 0.0f};

    const size_t TH = (size_t)TT * HH;

    for (int t = 0; t < TT; ++t) {
        /* ---- stage A = [h | x] as bf16 hi/lo ---- */
        if (tid < 32) {
            int s = (4 * t) / Lsm[tid];
            SGs[tid] = (s > 3) ? 3 : s;
        }
        const float* hb = d_h[t & 1];
        for (int i = tid; i < 32 * 256; i += 256) {
            int r = i >> 8, c = i & 255;
            float v = hb[(grp * 32 + r) * HH + c];
            __nv_bfloat16 hi = __float2bfloat16(v);
            Ahi[r * A_STRIDE + c] = hi;
            Alo[r * A_STRIDE + c] = __float2bfloat16(v - __bfloat162float(hi));
        }
        for (int i = tid; i < 32 * 128; i += 256) {
            int r = i >> 7, c = i & 127;
            float v = x[(size_t)BGs[r] * (TT * II) + (size_t)t * II + c];
            __nv_bfloat16 hi = __float2bfloat16(v);
            Ahi[r * A_STRIDE + 256 + c] = hi;
            Alo[r * A_STRIDE + 256 + c] = __float2bfloat16(v - __bfloat162float(hi));
        }
        __syncthreads();

        /* ---- GEMM: warp tile M16 x N16 (one gate type), K=384, 3-pass bf16 split ---- */
        float acc0[4] = {0.f, 0.f, 0.f, 0.f};
        float acc1[4] = {0.f, 0.f, 0.f, 0.f};
        {
            const int sr0  = SGs[row_base + g];
            const int sr1  = SGs[row_base + g + 8];
            const int stop = SGs[row_base];          /* max (lens sorted asc) */
            const int sbot = SGs[row_base + 15];     /* min */
            const int nrow0 = wn * 256 + nsl * 16 + g;   /* B frag0 weight row */
            const int nrow1 = nrow0 + 8;

            const unsigned* arow0h = (const unsigned*)(Ahi + (row_base + g) * A_STRIDE);
            const unsigned* arow1h = (const unsigned*)(Ahi + (row_base + g + 8) * A_STRIDE);
            const unsigned* arow0l = (const unsigned*)(Alo + (row_base + g) * A_STRIDE);
            const unsigned* arow1l = (const unsigned*)(Alo + (row_base + g + 8) * A_STRIDE);

            for (int s = sbot; s <= stop; ++s) {
                const unsigned mk0 = (sr0 == s) ? 0xFFFFFFFFu : 0u;
                const unsigned mk1 = (sr1 == s) ? 0xFFFFFFFFu : 0u;
                const unsigned* bh0 = (const unsigned*)(d_Whi + ((size_t)s * NROWS + nrow0) * KK);
                const unsigned* bh1 = (const unsigned*)(d_Whi + ((size_t)s * NROWS + nrow1) * KK);
                const unsigned* bl0 = (const unsigned*)(d_Wlo + ((size_t)s * NROWS + nrow0) * KK);
                const unsigned* bl1 = (const unsigned*)(d_Wlo + ((size_t)s * NROWS + nrow1) * KK);

                #pragma unroll
                for (int k0 = 0; k0 < KK; k0 += 16) {
                    const int ka = (k0 >> 1) + tig;   /* u32 index of bf16 pair (k0+2*tig) */
                    unsigned ah0 = arow0h[ka]     & mk0;
                    unsigned ah1 = arow1h[ka]     & mk1;
                    unsigned ah2 = arow0h[ka + 4] & mk0;
                    unsigned ah3 = arow1h[ka + 4] & mk1;
                    unsigned al0 = arow0l[ka]     & mk0;
                    unsigned al1 = arow1l[ka]     & mk1;
                    unsigned al2 = arow0l[ka + 4] & mk0;
                    unsigned al3 = arow1l[ka + 4] & mk1;

                    unsigned b00 = bh0[ka], b01 = bh0[ka + 4];
                    unsigned b10 = bh1[ka], b11 = bh1[ka + 4];
                    unsigned c00 = bl0[ka], c01 = bl0[ka + 4];
                    unsigned c10 = bl1[ka], c11 = bl1[ka + 4];

                    MMA_BF16(acc0, ah0, ah1, ah2, ah3, b00, b01);  /* hi*hi */
                    MMA_BF16(acc1, ah0, ah1, ah2, ah3, b10, b11);
                    MMA_BF16(acc0, ah0, ah1, ah2, ah3, c00, c01);  /* hi*lo(W) */
                    MMA_BF16(acc1, ah0, ah1, ah2, ah3, c10, c11);
                    MMA_BF16(acc0, al0, al1, al2, al3, b00, b01);  /* lo(A)*hi */
                    MMA_BF16(acc1, al0, al1, al2, al3, b10, b11);
                }
            }
        }

        /* ---- dump accumulators to gate smem [32][65] ---- */
        {
            const int r0 = row_base + g;
            const int cb = wn * 16 + 2 * tig;
            Gm[r0 * G_STRIDE + cb]           = acc0[0];
            Gm[r0 * G_STRIDE + cb + 1]       = acc0[1];
            Gm[(r0 + 8) * G_STRIDE + cb]     = acc0[2];
            Gm[(r0 + 8) * G_STRIDE + cb + 1] = acc0[3];
            Gm[r0 * G_STRIDE + cb + 8]           = acc1[0];
            Gm[r0 * G_STRIDE + cb + 9]           = acc1[1];
            Gm[(r0 + 8) * G_STRIDE + cb + 8]     = acc1[2];
            Gm[(r0 + 8) * G_STRIDE + cb + 9]     = acc1[3];
        }
        __syncthreads();

        /* ---- pointwise LSTM cell: thread owns (bl,hl) pairs tid, tid+256 ---- */
        #pragma unroll
        for (int q = 0; q < 2; ++q) {
            const int p  = tid + q * 256;
            const int bl = p >> 4, hl = p & 15;
            const int sg = SGs[bl];
            float ig = Gm[bl * G_STRIDE + hl]      + Bs[sg * 64 + hl];
            float fg = Gm[bl * G_STRIDE + 16 + hl] + Bs[sg * 64 + 16 + hl];
            float gg = Gm[bl * G_STRIDE + 32 + hl] + Bs[sg * 64 + 32 + hl];
            float og = Gm[bl * G_STRIDE + 48 + hl] + Bs[sg * 64 + 48 + hl];
            float si = 1.0f / (1.0f + __expf(-ig));
            float sf = 1.0f / (1.0f + __expf(-fg));
            float so = 1.0f / (1.0f + __expf(-og));
            float tg = tanhf(gg);
            float cn = sf * creg[q] + si * tg;
            float hn = so * tanhf(cn);
            const int  L     = Lsm[bl];
            const bool valid = (t < L);
            if (valid) { creg[q] = cn; hreg[q] = hn; }
            const int hg = nsl * 16 + hl;
            const int bg = BGs[bl];
            d_h[(t + 1) & 1][(grp * 32 + bl) * HH + hg] = hreg[q];
            out[(size_t)bg * TH + (size_t)t * HH + hg] = valid ? hn : 0.0f;
            if (t + 1 == L)
                out[(size_t)BB * TH + (size_t)bg * HH + hg] = hn;
        }

        /* ---- per-group barrier (16 CTAs) ---- */
        __syncthreads();
        if (tid == 0) {
            __threadfence();
            unsigned old = atomicAdd(&d_cnt[grp], 1u);
            if (old == BLK_PER_GRP - 1) {
                d_cnt[grp] = 0u;
                __threadfence();
                atomicExch(&d_phase[grp], (unsigned)(t + 1));
            } else {
                while (atomicAdd(&d_phase[grp], 0u) < (unsigned)(t + 1)) {
                    __nanosleep(64);
                }
            }
            __threadfence();
        }
        __syncthreads();
    }
}

/* ------------------------------------------------------------------ */
extern "C" void kernel_launch(void* const* d_in, const int* in_sizes, int n_in,
                              void* d_out, int out_size)
{
    /* defensively map inputs by element count (dict order: x, mask, W_ih,
       W_hh, b_ih, b_hh) */
    const float* x   = nullptr;
    const void*  msk = nullptr;
    const float* Wih = nullptr;
    const float* Whh = nullptr;
    const float* bih = nullptr;
    const float* bhh = nullptr;
    for (int i = 0; i < n_in; ++i) {
        int sz = in_sizes[i];
        if (sz == BB * TT * II)            x   = (const float*)d_in[i];
        else if (sz == BB * TT)            msk = d_in[i];
        else if (sz == SS * NROWS * II)    Wih = (const float*)d_in[i];
        else if (sz == SS * NROWS * HH)    Whh = (const float*)d_in[i];
        else if (sz == SS * NROWS) {
            if (!bih) bih = (const float*)d_in[i];
            else      bhh = (const float*)d_in[i];
        }
    }
    if (!x)   x   = (const float*)d_in[0];
    if (!msk) msk = d_in[1];
    if (!Wih) Wih = (const float*)d_in[2];
    if (!Whh) Whh = (const float*)d_in[3];
    if (!bih) bih = (const float*)d_in[4];
    if (!bhh) bhh = (const float*)d_in[5];
    float* out = (float*)d_out;

    cudaFuncSetAttribute(lstm_kernel,
                         cudaFuncAttributeMaxDynamicSharedMemorySize,
                         SMEM_BYTES);

    setup_kernel<<<1, 256>>>(msk);
    pack_kernel<<<1024, 256>>>(Wih, Whh, bih, bhh);
    lstm_kernel<<<NBLK, 256, SMEM_BYTES>>>(x, out);
}

// round 4
// speedup vs baseline: 1.4827x; 1.4827x over previous
#include <cuda_runtime.h>
#include <cuda_bf16.h>
#include <cstdint>
#include <cstddef>

#define BB 256
#define TT 512
#define II 128
#define HH 256
#define SS 4
#define KK 384            /* H + I */
#define NROWS 1024        /* 4H */
#define NBLK 128
#define NGRP 8
#define BLK_PER_GRP 16
#define NK0 24            /* KK/16 k-chunks */

#define A_STRIDE 392      /* 384 + 8 pad (bf16 elems) to break LDS bank conflicts */
#define G_STRIDE 65       /* gate smem row stride (floats) */

/* shared memory layout (bytes) */
#define SM_AHI   0
#define SM_ALO   25088                 /* 32*392*2 */
#define SM_GATES 50176                 /* 32*65*4 = 8320 */
#define SM_BIAS  58496                 /* 4*64*4 = 1024 */
#define SM_LEN   59520                 /* 32*4 */
#define SM_BG    59648                 /* 32*4 */
#define SM_SEG   59776                 /* 32*4 */
#define SMEM_BYTES 59904

/* ------------------------------------------------------------------ */
/* device globals (scratch)                                            */
/* ------------------------------------------------------------------ */
__device__ int d_len[BB];
__device__ int d_sorted[BB];        /* sorted position -> global batch  */
__device__ int d_len_sorted[BB];
/* W pre-swizzled to MMA fragment order:
   uint4 index = (((s*16+nsl)*4+wn)*24 + k0i)*64 + plane*32 + lane
   u32 j within uint4: j=0 b(row nrow0, ka) j=1 b(nrow0, ka+4)
                       j=2 b(nrow1, ka)     j=3 b(nrow1, ka+4)
   plane 0 = hi bf16, plane 1 = lo (residual) bf16                     */
__device__ uint4 d_Wp4[4 * 16 * 4 * NK0 * 64];   /* 6.29 MB */
__device__ float d_bias[SS * NROWS];
__device__ float d_h[2][BB * HH];   /* h state by sorted position, ping-pong */
__device__ unsigned d_cnt[NGRP];
__device__ volatile unsigned d_phase[NGRP];

/* ------------------------------------------------------------------ */
/* mask dtype sniff (mask[0][0], mask[0][1] guaranteed true: len>=256) */
/* ------------------------------------------------------------------ */
__device__ __forceinline__ int sniff_mode(const unsigned char* mb)
{
    if (mb[0] == 1 && mb[1] == 1)      return 0;   /* u8  */
    else if (mb[0] == 1)               return 1;   /* i32 */
    else if (mb[0] == 0 && mb[1] == 0) return 2;   /* f32 */
    else                               return 3;   /* 16-bit */
}

/* lengths: one block per batch */
__global__ void len_kernel(const void* mask)
{
    __shared__ int scnt;
    const int b = blockIdx.x, tid = threadIdx.x;
    const unsigned char* mb = (const unsigned char*)mask;
    const int mode = sniff_mode(mb);
    if (tid == 0) scnt = 0;
    __syncthreads();
    int c = 0;
    #pragma unroll
    for (int q = 0; q < 2; ++q) {
        long idx = (long)b * TT + tid + q * 256;
        bool v;
        if (mode == 0)      v = mb[idx] != 0;
        else if (mode == 1) v = ((const int*)mask)[idx] != 0;
        else if (mode == 2) v = ((const float*)mask)[idx] != 0.0f;
        else                v = ((const unsigned short*)mask)[idx] != 0;
        c += v ? 1 : 0;
    }
    /* warp reduce then shared atomic */
    for (int o = 16; o > 0; o >>= 1) c += __shfl_down_sync(0xFFFFFFFFu, c, o);
    if ((tid & 31) == 0) atomicAdd(&scnt, c);
    __syncthreads();
    if (tid == 0) d_len[b] = (scnt < 1) ? 1 : scnt;
}

/* counting sort by length + barrier reset */
__global__ void sort_kernel()
{
    const int tid = threadIdx.x;
    __shared__ int L[BB];
    L[tid] = d_len[tid];
    __syncthreads();
    int myL = L[tid], r = 0;
    for (int b = 0; b < BB; ++b) {
        int Lb = L[b];
        if (Lb < myL || (Lb == myL && b < tid)) r++;
    }
    d_sorted[r] = tid;
    d_len_sorted[r] = myL;
    if (tid < NGRP) { d_cnt[tid] = 0u; d_phase[tid] = 0u; }
}

/* ------------------------------------------------------------------ */
/* pack: W -> fragment-order hi/lo bf16 planes; bias sum; zero h[0]    */
/* ------------------------------------------------------------------ */
__device__ __forceinline__ unsigned pack_bf(__nv_bfloat16 a, __nv_bfloat16 b)
{
    return (unsigned)__bfloat16_as_ushort(a)
         | ((unsigned)__bfloat16_as_ushort(b) << 16);
}

__global__ void pack_kernel(const float* __restrict__ Wih,
                            const float* __restrict__ Whh,
                            const float* __restrict__ bih,
                            const float* __restrict__ bhh)
{
    const int totalW = 4 * 16 * 4 * NK0 * 64 * 4;   /* u32 count = 1,572,864 */
    const int totalB = SS * NROWS;                  /* 4096  */
    const int totalH = BB * HH;                     /* 65536 */
    const int total  = totalW + totalB + totalH;
    unsigned* Wp = (unsigned*)d_Wp4;
    for (int i = blockIdx.x * blockDim.x + threadIdx.x; i < total;
         i += gridDim.x * blockDim.x) {
        if (i < totalW) {
            int j     = i & 3;
            int lane  = (i >> 2) & 31;
            int plane = (i >> 7) & 1;
            int rem   = i >> 8;
            int k0i   = rem % NK0;  rem /= NK0;
            int wn    = rem & 3;    rem >>= 2;
            int nsl   = rem & 15;
            int s     = rem >> 4;
            int g = lane >> 2, tig = lane & 3;
            int row = wn * 256 + nsl * 16 + g + ((j & 2) ? 8 : 0);
            int k = k0i * 16 + (j & 1) * 8 + 2 * tig;
            float v0, v1;
            if (k < HH) {
                const float* p = Whh + ((size_t)s * NROWS + row) * HH + k;
                v0 = p[0]; v1 = p[1];
            } else {
                const float* p = Wih + ((size_t)s * NROWS + row) * II + (k - HH);
                v0 = p[0]; v1 = p[1];
            }
            __nv_bfloat16 h0 = __float2bfloat16(v0);
            __nv_bfloat16 h1 = __float2bfloat16(v1);
            if (plane == 0) {
                Wp[i] = pack_bf(h0, h1);
            } else {
                __nv_bfloat16 l0 = __float2bfloat16(v0 - __bfloat162float(h0));
                __nv_bfloat16 l1 = __float2bfloat16(v1 - __bfloat162float(h1));
                Wp[i] = pack_bf(l0, l1);
            }
        } else if (i < totalW + totalB) {
            int j = i - totalW;
            d_bias[j] = bih[j] + bhh[j];
        } else {
            int j = i - totalW - totalB;
            d_h[0][j] = 0.0f;
        }
    }
}

/* ------------------------------------------------------------------ */
/* mma helper: m16n8k16 row.col f32.bf16.bf16.f32                      */
/* ------------------------------------------------------------------ */
#define MMA_BF16(acc, a0, a1, a2, a3, b0, b1)                               \
    asm volatile(                                                           \
        "mma.sync.aligned.m16n8k16.row.col.f32.bf16.bf16.f32 "              \
        "{%0,%1,%2,%3}, {%4,%5,%6,%7}, {%8,%9}, {%0,%1,%2,%3};"             \
        : "+f"((acc)[0]), "+f"((acc)[1]), "+f"((acc)[2]), "+f"((acc)[3])    \
        : "r"(a0), "r"(a1), "r"(a2), "r"(a3), "r"(b0), "r"(b1))

__device__ __forceinline__ float sigm_fast(float v)
{
    return __fdividef(1.0f, 1.0f + __expf(-v));
}
__device__ __forceinline__ float tanh_fast(float v)
{
    /* 1 - 2/(e^{2v}+1): saturates cleanly at +/-1, no NaN */
    return 1.0f - 2.0f * __fdividef(1.0f, 1.0f + __expf(2.0f * v));
}

/* ------------------------------------------------------------------ */
/* persistent LSTM kernel: 128 CTAs = 8 batch-groups x 16 h-slices     */
/* ------------------------------------------------------------------ */
__global__ void __launch_bounds__(256, 1)
lstm_kernel(const float* __restrict__ x, float* __restrict__ out)
{
    extern __shared__ unsigned char sm[];
    __nv_bfloat16* Ahi = (__nv_bfloat16*)(sm + SM_AHI);
    __nv_bfloat16* Alo = (__nv_bfloat16*)(sm + SM_ALO);
    float* Gm  = (float*)(sm + SM_GATES);
    float* Bs  = (float*)(sm + SM_BIAS);
    int*   Lsm = (int*)(sm + SM_LEN);
    int*   BGs = (int*)(sm + SM_BG);
    int*   SGs = (int*)(sm + SM_SEG);

    const int tid  = threadIdx.x;
    const int bid  = blockIdx.x;
    const int grp  = bid >> 4;      /* batch group 0..7   */
    const int nsl  = bid & 15;      /* h-slice     0..15  */
    const int warp = tid >> 5, lane = tid & 31;
    const int wm = warp >> 2, wn = warp & 3;   /* 2 M-warps x 4 N-warps */
    const int g  = lane >> 2, tig = lane & 3;
    const int row_base = wm * 16;

    if (tid < 32) {
        int p = grp * 32 + tid;
        BGs[tid] = d_sorted[p];
        Lsm[tid] = d_len_sorted[p];
    }
    {   /* bias cache: [seg][type*16+hl] for this block's 64 gate rows */
        int s = tid >> 6, c = tid & 63;
        int type = c >> 4, hl = c & 15;
        Bs[tid] = d_bias[s * NROWS + type * 256 + nsl * 16 + hl];
    }
    __syncthreads();

    /* each thread statically owns 2 (batch,h) cells: p=tid and p=tid+256 */
    float hreg[2] = {0.0f, 0.0f};
    float creg[2] = {0.0f, 0.0f};

    const size_t TH = (size_t)TT * HH;
    /* per-warp fragment-order W base (s added in loop) */
    const uint4* wblk = d_Wp4 + ((size_t)(nsl * 4 + wn)) * (NK0 * 64);

    for (int t = 0; t < TT; ++t) {
        /* ---- stage A = [h | x] as bf16 hi/lo ---- */
        if (tid < 32) {
            int s = (4 * t) / Lsm[tid];
            SGs[tid] = (s > 3) ? 3 : s;
        }
        const float* hb = d_h[t & 1];
        #pragma unroll
        for (int q = 0; q < 32; ++q) {
            int i = tid + q * 256;
            int r = i >> 8, c = i & 255;
            float v = hb[(grp * 32 + r) * HH + c];
            __nv_bfloat16 hi = __float2bfloat16(v);
            Ahi[r * A_STRIDE + c] = hi;
            Alo[r * A_STRIDE + c] = __float2bfloat16(v - __bfloat162float(hi));
        }
        #pragma unroll
        for (int q = 0; q < 16; ++q) {
            int i = tid + q * 256;
            int r = i >> 7, c = i & 127;
            float v = x[(size_t)BGs[r] * (TT * II) + (size_t)t * II + c];
            __nv_bfloat16 hi = __float2bfloat16(v);
            Ahi[r * A_STRIDE + 256 + c] = hi;
            Alo[r * A_STRIDE + 256 + c] = __float2bfloat16(v - __bfloat162float(hi));
        }
        __syncthreads();

        /* ---- GEMM: warp tile M16 x N16, K=384, 3-pass bf16 split ---- */
        float acc0[4] = {0.f, 0.f, 0.f, 0.f};
        float acc1[4] = {0.f, 0.f, 0.f, 0.f};
        {
            const int sr0  = SGs[row_base + g];
            const int sr1  = SGs[row_base + g + 8];
            const int stop = SGs[row_base];          /* max (lens sorted asc) */
            const int sbot = SGs[row_base + 15];     /* min */

            const unsigned* arow0h = (const unsigned*)(Ahi + (row_base + g) * A_STRIDE);
            const unsigned* arow1h = (const unsigned*)(Ahi + (row_base + g + 8) * A_STRIDE);
            const unsigned* arow0l = (const unsigned*)(Alo + (row_base + g) * A_STRIDE);
            const unsigned* arow1l = (const unsigned*)(Alo + (row_base + g + 8) * A_STRIDE);

            for (int s = sbot; s <= stop; ++s) {
                const unsigned mk0 = (sr0 == s) ? 0xFFFFFFFFu : 0u;
                const unsigned mk1 = (sr1 == s) ? 0xFFFFFFFFu : 0u;
                const uint4* wp = wblk + (size_t)s * (16 * 4 * NK0 * 64);

                #pragma unroll
                for (int k0i = 0; k0i < NK0; ++k0i) {
                    /* coalesced fragment loads: 2 x LDG.128 per lane */
                    uint4 bh = wp[k0i * 64 + lane];        /* b00 b01 b10 b11 */
                    uint4 bl = wp[k0i * 64 + 32 + lane];   /* c00 c01 c10 c11 */

                    const int ka = k0i * 8 + tig;
                    unsigned ah0 = arow0h[ka]     & mk0;
                    unsigned ah1 = arow1h[ka]     & mk1;
                    unsigned ah2 = arow0h[ka + 4] & mk0;
                    unsigned ah3 = arow1h[ka + 4] & mk1;
                    unsigned al0 = arow0l[ka]     & mk0;
                    unsigned al1 = arow1l[ka]     & mk1;
                    unsigned al2 = arow0l[ka + 4] & mk0;
                    unsigned al3 = arow1l[ka + 4] & mk1;

                    MMA_BF16(acc0, ah0, ah1, ah2, ah3, bh.x, bh.y);  /* hi*hi */
                    MMA_BF16(acc1, ah0, ah1, ah2, ah3, bh.z, bh.w);
                    MMA_BF16(acc0, ah0, ah1, ah2, ah3, bl.x, bl.y);  /* hi*loW */
                    MMA_BF16(acc1, ah0, ah1, ah2, ah3, bl.z, bl.w);
                    MMA_BF16(acc0, al0, al1, al2, al3, bh.x, bh.y);  /* loA*hi */
                    MMA_BF16(acc1, al0, al1, al2, al3, bh.z, bh.w);
                }
            }
        }

        /* ---- dump accumulators to gate smem [32][65] ---- */
        {
            const int r0 = row_base + g;
            const int cb = wn * 16 + 2 * tig;
            Gm[r0 * G_STRIDE + cb]           = acc0[0];
            Gm[r0 * G_STRIDE + cb + 1]       = acc0[1];
            Gm[(r0 + 8) * G_STRIDE + cb]     = acc0[2];
            Gm[(r0 + 8) * G_STRIDE + cb + 1] = acc0[3];
            Gm[r0 * G_STRIDE + cb + 8]       = acc1[0];
            Gm[r0 * G_STRIDE + cb + 9]       = acc1[1];
            Gm[(r0 + 8) * G_STRIDE + cb + 8] = acc1[2];
            Gm[(r0 + 8) * G_STRIDE + cb + 9] = acc1[3];
        }
        __syncthreads();

        /* ---- pointwise LSTM cell: thread owns (bl,hl) pairs tid, tid+256 ---- */
        #pragma unroll
        for (int q = 0; q < 2; ++q) {
            const int p  = tid + q * 256;
            const int bl = p >> 4, hl = p & 15;
            const int sg = SGs[bl];
            float ig = Gm[bl * G_STRIDE + hl]      + Bs[sg * 64 + hl];
            float fg = Gm[bl * G_STRIDE + 16 + hl] + Bs[sg * 64 + 16 + hl];
            float gg = Gm[bl * G_STRIDE + 32 + hl] + Bs[sg * 64 + 32 + hl];
            float og = Gm[bl * G_STRIDE + 48 + hl] + Bs[sg * 64 + 48 + hl];
            float si = sigm_fast(ig);
            float sf = sigm_fast(fg);
            float so = sigm_fast(og);
            float tg = tanh_fast(gg);
            float cn = sf * creg[q] + si * tg;
            float hn = so * tanh_fast(cn);
            const int  L     = Lsm[bl];
            const bool valid = (t < L);
            if (valid) { creg[q] = cn; hreg[q] = hn; }
            const int hg = nsl * 16 + hl;
            const int bg = BGs[bl];
            d_h[(t + 1) & 1][(grp * 32 + bl) * HH + hg] = hreg[q];
            out[(size_t)bg * TH + (size_t)t * HH + hg] = valid ? hn : 0.0f;
            if (t + 1 == L)
                out[(size_t)BB * TH + (size_t)bg * HH + hg] = hn;
        }

        /* ---- per-group barrier (16 CTAs) ---- */
        __syncthreads();
        if (tid == 0) {
            __threadfence();
            unsigned old = atomicAdd(&d_cnt[grp], 1u);
            if (old == BLK_PER_GRP - 1) {
                d_cnt[grp] = 0u;
                __threadfence();
                d_phase[grp] = (unsigned)(t + 1);
            } else {
                while (d_phase[grp] < (unsigned)(t + 1)) {
                    __nanosleep(32);
                }
            }
            __threadfence();
        }
        __syncthreads();
    }
}

/* ------------------------------------------------------------------ */
extern "C" void kernel_launch(void* const* d_in, const int* in_sizes, int n_in,
                              void* d_out, int out_size)
{
    /* map inputs by element count (dict order: x, mask, W_ih, W_hh, b_ih, b_hh) */
    const float* x   = nullptr;
    const void*  msk = nullptr;
    const float* Wih = nullptr;
    const float* Whh = nullptr;
    const float* bih = nullptr;
    const float* bhh = nullptr;
    for (int i = 0; i < n_in; ++i) {
        int sz = in_sizes[i];
        if (sz == BB * TT * II)            x   = (const float*)d_in[i];
        else if (sz == BB * TT)            msk = d_in[i];
        else if (sz == SS * NROWS * II)    Wih = (const float*)d_in[i];
        else if (sz == SS * NROWS * HH)    Whh = (const float*)d_in[i];
        else if (sz == SS * NROWS) {
            if (!bih) bih = (const float*)d_in[i];
            else      bhh = (const float*)d_in[i];
        }
    }
    if (!x)   x   = (const float*)d_in[0];
    if (!msk) msk = d_in[1];
    if (!Wih) Wih = (const float*)d_in[2];
    if (!Whh) Whh = (const float*)d_in[3];
    if (!bih) bih = (const float*)d_in[4];
    if (!bhh) bhh = (const float*)d_in[5];
    float* out = (float*)d_out;

    cudaFuncSetAttribute(lstm_kernel,
                         cudaFuncAttributeMaxDynamicSharedMemorySize,
                         SMEM_BYTES);

    len_kernel<<<BB, 256>>>(msk);
    sort_kernel<<<1, BB>>>();
    pack_kernel<<<512, 256>>>(Wih, Whh, bih, bhh);
    lstm_kernel<<<NBLK, 256, SMEM_BYTES>>>(x, out);
}